// round 5
// baseline (speedup 1.0000x reference)
#include <cuda_runtime.h>
#include <math.h>

#define Nn    16384
#define Bg    16
#define NPG   1024
#define Kk    12
#define DM    128
#define DH    256
#define Ll    3

// ---------------- device scratch (no allocs allowed) ----------------
__device__ float g_h  [Nn * DM];
__device__ float g_ta [Nn * DH];
__device__ float g_tb [Nn * DH];
__device__ float g_ea [Nn * Kk * 4];
__device__ int   g_knn[Nn * Kk];
__device__ float g_gl [Nn];
__device__ float g_ghid[Nn * DM];
__device__ float g_part [Bg * 8 * DM];
__device__ float g_part2[Bg * 8 * DM];

// split (hi,lo) buffers, 16B aligned via uint4
__device__ uint4 g_ih2 [Nn * DM / 2];   // in_hidden split
__device__ uint4 g_h2  [Nn * DM / 2];   // h split
__device__ uint4 g_s2  [Nn * DH / 2];   // edge-agg split
__device__ uint4 g_agg2[Nn * DM / 2];
__device__ uint4 g_uh2 [Nn * DH / 2];

// split weights: layout (uint2 units)
// [0,16384) in_W2 | [16384,32768) gate_W1 | per l: base=32768+l*196608:
//   +0 W1p(128x512 packed) +65536 W2(256x128) +98304 U1a(128x256)
//   +131072 U1b(128x256) +163840 U2(256x128)
#define WS_TOTAL 622592
#define WS_INW2  0
#define WS_GATE  16384
#define WS_L(l)  (32768 + (l) * 196608)
__device__ uint4 g_ws[WS_TOTAL / 2];

__device__ __forceinline__ float siluf(float v) { return v / (1.f + expf(-v)); }

__device__ __forceinline__ unsigned f2tf32(float f) {
    unsigned u;
    asm("cvt.rna.tf32.f32 %0, %1;" : "=r"(u) : "f"(f));
    return u;
}
__device__ __forceinline__ uint2 split_tf32(float f) {
    unsigned hi = f2tf32(f);
    float res = f - __uint_as_float(hi);
    unsigned lo = f2tf32(res);
    return make_uint2(hi, lo);
}

__device__ __forceinline__ void mma_tf32(float& c0, float& c1, float& c2, float& c3,
                                         unsigned a0, unsigned a1, unsigned a2, unsigned a3,
                                         unsigned b0, unsigned b1) {
    asm volatile("mma.sync.aligned.m16n8k8.row.col.f32.tf32.tf32.f32 "
                 "{%0,%1,%2,%3},{%4,%5,%6,%7},{%8,%9},{%0,%1,%2,%3};"
                 : "+f"(c0), "+f"(c1), "+f"(c2), "+f"(c3)
                 : "r"(a0), "r"(a1), "r"(a2), "r"(a3), "r"(b0), "r"(b1));
}

// ---------------- weight split + pack ----------------
__global__ __launch_bounds__(256) void wsplit_kernel(
    const float* __restrict__ in_W2, const float* __restrict__ gate_W1,
    const float* __restrict__ msg_W1, const float* __restrict__ msg_W2,
    const float* __restrict__ upd_W1, const float* __restrict__ upd_W2,
    uint2* __restrict__ ws) {
    int id = blockIdx.x * 256 + threadIdx.x;
    if (id >= WS_TOTAL) return;
    float v;
    if (id < 16384) v = in_W2[id];
    else if (id < 32768) v = gate_W1[id - 16384];
    else {
        int t = id - 32768;
        int l = t / 196608, r = t % 196608;
        if (r < 65536) {
            int k = r >> 9, n = r & 511;
            const float* W1 = msg_W1 + (size_t)l * 260 * 256;
            v = (n < 256) ? W1[k * 256 + n] : W1[(128 + k) * 256 + (n - 256)];
        } else if (r < 98304) {
            v = msg_W2[(size_t)l * 32768 + (r - 65536)];
        } else if (r < 131072) {
            v = upd_W1[(size_t)l * 65536 + (r - 98304)];
        } else if (r < 163840) {
            v = upd_W1[(size_t)l * 65536 + 32768 + (r - 131072)];
        } else {
            v = upd_W2[(size_t)l * 32768 + (r - 163840)];
        }
    }
    ws[id] = split_tf32(v);
}

// ---------------- KNN + edge attrs ----------------
__global__ __launch_bounds__(256) void knn_kernel(const float* __restrict__ x,
                                                  int* __restrict__ knn,
                                                  float* __restrict__ ea) {
    __shared__ float px[NPG], py[NPG], d2[NPG];
    __shared__ unsigned long long wred[8];
    const float INF = __int_as_float(0x7f800000);
    int n = blockIdx.x;
    int g = n >> 10;
    int li = n & 1023;
    int base = g << 10;
    int tid = threadIdx.x;
    int lane = tid & 31, warp = tid >> 5;
    for (int t = tid; t < NPG; t += 256) {
        px[t] = x[(base + t) * 3 + 1];
        py[t] = x[(base + t) * 3 + 2];
    }
    __syncthreads();
    float mx = px[li], my = py[li];
    for (int t = tid; t < NPG; t += 256) {
        float dx = __fsub_rn(px[t], mx);
        float dy = __fsub_rn(py[t], my);
        float v = __fadd_rn(__fmul_rn(dx, dx), __fmul_rn(dy, dy));
        d2[t] = (t == li) ? INF : v;
    }
    __syncthreads();
    for (int p = 0; p < Kk; ++p) {
        float bd = INF;
        int bi = 1 << 20;
#pragma unroll
        for (int r = 0; r < 4; ++r) {
            int t = tid + r * 256;
            float v = d2[t];
            if (v < bd || (v == bd && t < bi)) { bd = v; bi = t; }
        }
        unsigned long long key = ((unsigned long long)__float_as_uint(bd) << 32) | (unsigned)bi;
#pragma unroll
        for (int o = 16; o; o >>= 1) {
            unsigned long long other = __shfl_xor_sync(0xffffffffu, key, o);
            if (other < key) key = other;
        }
        if (lane == 0) wred[warp] = key;
        __syncthreads();
        if (tid == 0) {
            unsigned long long best = wred[0];
#pragma unroll
            for (int q = 1; q < 8; ++q) if (wred[q] < best) best = wred[q];
            int w = (int)(best & 0xffffffffu);
            knn[n * Kk + p] = base + w;
            float dpx = px[w] - mx, dpy = py[w] - my;
            float dist = sqrtf(dpx * dpx + dpy * dpy + 1e-12f);
            float ds = x[(base + w) * 3] - x[n * 3];
            float* e = ea + (n * Kk + p) * 4;
            e[0] = dpx; e[1] = dpy; e[2] = dist; e[3] = ds;
            d2[w] = INF;
        }
        __syncthreads();
    }
}

// ---------------- input MLP hidden (writes split) ----------------
__global__ void in_hidden_kernel(const float* __restrict__ x,
                                 const float* __restrict__ W1,
                                 const float* __restrict__ b1,
                                 uint2* __restrict__ out2) {
    int n = blockIdx.x;
    int j = threadIdx.x;
    float x0 = x[n * 3], x1 = x[n * 3 + 1], x2 = x[n * 3 + 2];
    float t = b1[j] + x0 * W1[j] + x1 * W1[DM + j] + x2 * W1[2 * DM + j];
    out2[n * DM + j] = split_tf32(siluf(t));
}

// ---------------- 3xTF32 GEMM on pre-split operands ----------------
// C = act( A0@B0 + (A1@B1) + bias + R ), all A/B pre-split uint2 (hi,lo).
// Columns < colSplit -> Cf0 (ld colSplit) + bias[col]; cols >= colSplit ->
// Cf1 (ld N-colSplit) + bias1. Cs0 (split out, ld N) only when colSplit==N.
__global__ __launch_bounds__(256, 2) void gemm3s(
    const uint2* __restrict__ A0, const uint2* __restrict__ B0, int K0,
    const uint2* __restrict__ A1, const uint2* __restrict__ B1, int K1,
    const float* __restrict__ bias, const float* __restrict__ bias1, float biasScale,
    int colSplit,
    const float* __restrict__ R,
    float* __restrict__ Cf0, float* __restrict__ Cf1, uint2* __restrict__ Cs0,
    int N, int act) {
    __shared__ __align__(32) uint2 As2[128][20];
    __shared__ __align__(32) uint2 Bs2[16][132];
    int tid = threadIdx.x;
    int lane = tid & 31, warp = tid >> 5;
    int wm = warp >> 1, wn = warp & 1;
    int gq = lane >> 2, ctg = lane & 3;
    int rowBase = blockIdx.y * 128, colBase = blockIdx.x * 128;

    float c[2][8][4];
#pragma unroll
    for (int t = 0; t < 2; ++t)
#pragma unroll
        for (int j = 0; j < 8; ++j)
#pragma unroll
            for (int e = 0; e < 4; ++e) c[t][j][e] = 0.f;

    int am = tid & 127;
    int aq = tid >> 7;
    int bn4 = tid & 31;
    int bk = tid >> 5;

    for (int part = 0; part < 2; ++part) {
        const uint2* A = part ? A1 : A0;
        const uint2* B = part ? B1 : B0;
        int K = part ? K1 : K0;
        if (A == nullptr) continue;
        const uint2* Arow = A + (size_t)(rowBase + am) * K;
        for (int k0 = 0; k0 < K; k0 += 16) {
#pragma unroll
            for (int i = 0; i < 2; ++i) {
                const uint4* src = (const uint4*)(Arow + k0 + aq * 8 + i * 4);
                uint4* dst = (uint4*)&As2[am][aq * 8 + i * 4];
                dst[0] = src[0];
                dst[1] = src[1];
            }
#pragma unroll
            for (int i = 0; i < 2; ++i) {
                int kr = bk + i * 8;
                const uint4* src = (const uint4*)(B + (size_t)(k0 + kr) * N + colBase + bn4 * 4);
                uint4* dst = (uint4*)&Bs2[kr][bn4 * 4];
                dst[0] = src[0];
                dst[1] = src[1];
            }
            __syncthreads();
#pragma unroll
            for (int ks = 0; ks < 16; ks += 8) {
                uint2 a0[2], a1[2], a2[2], a3[2];
#pragma unroll
                for (int t = 0; t < 2; ++t) {
                    int row = wm * 32 + t * 16 + gq;
                    a0[t] = As2[row][ks + ctg];
                    a1[t] = As2[row + 8][ks + ctg];
                    a2[t] = As2[row][ks + ctg + 4];
                    a3[t] = As2[row + 8][ks + ctg + 4];
                }
#pragma unroll
                for (int j = 0; j < 8; ++j) {
                    int col = wn * 64 + j * 8 + gq;
                    uint2 b0 = Bs2[ks + ctg][col];
                    uint2 b1 = Bs2[ks + ctg + 4][col];
#pragma unroll
                    for (int t = 0; t < 2; ++t) {
                        mma_tf32(c[t][j][0], c[t][j][1], c[t][j][2], c[t][j][3],
                                 a0[t].x, a1[t].x, a2[t].x, a3[t].x, b0.x, b1.x);
                        mma_tf32(c[t][j][0], c[t][j][1], c[t][j][2], c[t][j][3],
                                 a0[t].x, a1[t].x, a2[t].x, a3[t].x, b0.y, b1.y);
                        mma_tf32(c[t][j][0], c[t][j][1], c[t][j][2], c[t][j][3],
                                 a0[t].y, a1[t].y, a2[t].y, a3[t].y, b0.x, b1.x);
                    }
                }
            }
            __syncthreads();
        }
    }

#pragma unroll
    for (int t = 0; t < 2; ++t) {
#pragma unroll
        for (int half = 0; half < 2; ++half) {
            int r = rowBase + wm * 32 + t * 16 + gq + half * 8;
#pragma unroll
            for (int j = 0; j < 8; ++j) {
                int col = colBase + wn * 64 + j * 8 + ctg * 2;
                float v0 = c[t][j][half * 2 + 0];
                float v1 = c[t][j][half * 2 + 1];
                bool first = (col < colSplit);
                const float* bs = first ? bias : bias1;
                int cb = first ? col : col - colSplit;
                if (bs) { v0 += bs[cb] * biasScale; v1 += bs[cb + 1] * biasScale; }
                if (R) {
                    v0 += R[(size_t)r * N + col];
                    v1 += R[(size_t)r * N + col + 1];
                }
                if (act == 1) { v0 = siluf(v0); v1 = siluf(v1); }
                else if (act == 2) { v0 = tanhf(v0); v1 = tanhf(v1); }
                if (first) {
                    if (Cf0) *(float2*)&Cf0[(size_t)r * colSplit + col] = make_float2(v0, v1);
                    if (Cs0) {
                        uint2 s0 = split_tf32(v0), s1 = split_tf32(v1);
                        *(uint4*)&Cs0[(size_t)r * N + col] = make_uint4(s0.x, s0.y, s1.x, s1.y);
                    }
                } else {
                    *(float2*)&Cf1[(size_t)r * (N - colSplit) + cb] = make_float2(v0, v1);
                }
            }
        }
    }
}

// ---------------- per-edge hidden + silu + aggregate (writes split) ----------------
__global__ __launch_bounds__(256) void edge_kernel(const float* __restrict__ ta,
                                                   const float* __restrict__ tb,
                                                   const int* __restrict__ knn,
                                                   const float* __restrict__ ea,
                                                   const float* __restrict__ W1c,
                                                   uint2* __restrict__ s2) {
    __shared__ int   ksh[Kk];
    __shared__ float esh[Kk * 4];
    int n = blockIdx.x;
    int c = threadIdx.x;
    if (c < Kk) ksh[c] = knn[n * Kk + c];
    if (c < Kk * 4) esh[c] = ea[n * Kk * 4 + c];
    __syncthreads();
    float w0 = W1c[c], w1 = W1c[DH + c], w2 = W1c[2 * DH + c], w3 = W1c[3 * DH + c];
    float tav = ta[n * DH + c];
    float acc = 0.f;
#pragma unroll
    for (int j = 0; j < Kk; ++j) {
        int src = ksh[j];
        float v = tav + tb[src * DH + c]
                + esh[4 * j] * w0 + esh[4 * j + 1] * w1
                + esh[4 * j + 2] * w2 + esh[4 * j + 3] * w3;
        acc += siluf(v);
    }
    s2[n * DH + c] = split_tf32(acc);
}

// ---------------- graph norm: 3-kernel deterministic chain ----------------
__global__ void norm_s1(const float* __restrict__ h, float* __restrict__ part) {
    int b = blockIdx.x >> 3, sl = blockIdx.x & 7, c = threadIdx.x;
    int row0 = (b << 10) + (sl << 7);
    float acc = 0.f;
    for (int r = 0; r < 128; ++r) acc += h[(row0 + r) * DM + c];
    part[blockIdx.x * DM + c] = acc;
}
__global__ void norm_s2(float* __restrict__ h, const float* __restrict__ part,
                        const float* __restrict__ ms, float* __restrict__ part2) {
    int b = blockIdx.x >> 3, sl = blockIdx.x & 7, c = threadIdx.x;
    int row0 = (b << 10) + (sl << 7);
    float m = 0.f;
    for (int q = 0; q < 8; ++q) m += part[(b * 8 + q) * DM + c];
    m *= (1.f / 1024.f);
    float mv = m * ms[c];
    float acc = 0.f;
    for (int r = 0; r < 128; ++r) {
        float o = h[(row0 + r) * DM + c] - mv;
        h[(row0 + r) * DM + c] = o;
        acc += o * o;
    }
    part2[blockIdx.x * DM + c] = acc;
}
__global__ void norm_s3(float* __restrict__ h, const float* __restrict__ part2,
                        const float* __restrict__ w, const float* __restrict__ bb,
                        uint2* __restrict__ h2) {
    int b = blockIdx.x >> 3, sl = blockIdx.x & 7, c = threadIdx.x;
    int row0 = (b << 10) + (sl << 7);
    float v = 0.f;
    for (int q = 0; q < 8; ++q) v += part2[(b * 8 + q) * DM + c];
    v *= (1.f / 1024.f);
    float inv = 1.f / sqrtf(v + 1e-5f);
    float wc = w[c] * inv, bc = bb[c];
    for (int r = 0; r < 128; ++r) {
        float val = h[(row0 + r) * DM + c] * wc + bc;
        h[(row0 + r) * DM + c] = val;
        h2[(row0 + r) * DM + c] = split_tf32(val);
    }
}

// ---------------- gate logit GEMV ----------------
__global__ void gl_kernel(const float* __restrict__ ghid, const float* __restrict__ W2,
                          const float* __restrict__ b2, float* __restrict__ gl) {
    int node = blockIdx.x * 8 + (threadIdx.x >> 5);
    int lane = threadIdx.x & 31;
    float acc = 0.f;
#pragma unroll
    for (int r = 0; r < 4; ++r) acc += ghid[node * DM + lane + 32 * r] * W2[lane + 32 * r];
#pragma unroll
    for (int o = 16; o; o >>= 1) acc += __shfl_down_sync(0xffffffffu, acc, o);
    if (lane == 0) gl[node] = acc + b2[0];
}

// ---------------- softmax pool + head ----------------
__global__ __launch_bounds__(1024) void pool_head(const float* __restrict__ h,
                                                  const float* __restrict__ gl,
                                                  const float* __restrict__ hW1,
                                                  const float* __restrict__ hb1,
                                                  const float* __restrict__ hW2,
                                                  const float* __restrict__ hb2,
                                                  float* __restrict__ out) {
    __shared__ float red[1024];
    __shared__ float ash[1024];
    __shared__ float pool[1024];
    __shared__ float pvec[128];
    __shared__ float hid[128];
    int g = blockIdx.x, tid = threadIdx.x;
    float gv = gl[g * NPG + tid];
    red[tid] = gv;
    __syncthreads();
    for (int s = 512; s > 0; s >>= 1) {
        if (tid < s) red[tid] = fmaxf(red[tid], red[tid + s]);
        __syncthreads();
    }
    float gmax = red[0];
    __syncthreads();
    float e = expf(gv - gmax);
    red[tid] = e;
    __syncthreads();
    for (int s = 512; s > 0; s >>= 1) {
        if (tid < s) red[tid] += red[tid + s];
        __syncthreads();
    }
    float ssum = red[0];
    __syncthreads();
    ash[tid] = e / ssum;
    __syncthreads();
    int r = tid >> 7, c = tid & 127;
    float acc = 0.f;
    for (int n = r; n < NPG; n += 8)
        acc += ash[n] * h[(g * NPG + n) * DM + c];
    pool[tid] = acc;
    __syncthreads();
    if (tid < 128) {
        float p = 0.f;
        for (int q = 0; q < 8; ++q) p += pool[q * 128 + tid];
        pvec[tid] = p;
    }
    __syncthreads();
    if (tid < 128) {
        float t = hb1[tid];
        for (int k = 0; k < 128; ++k) t += pvec[k] * hW1[k * DM + tid];
        hid[tid] = siluf(t);
    }
    __syncthreads();
    if (tid < 128) red[tid] = hid[tid] * hW2[tid];
    __syncthreads();
    for (int s = 64; s > 0; s >>= 1) {
        if (tid < s) red[tid] += red[tid + s];
        __syncthreads();
    }
    if (tid == 0) out[g] = red[0] + hb2[0];
}

// ---------------- host orchestration ----------------
extern "C" void kernel_launch(void* const* d_in, const int* in_sizes, int n_in,
                              void* d_out, int out_size) {
    (void)in_sizes; (void)n_in; (void)out_size;
    const float* x      = (const float*)d_in[0];
    const float* in_W1  = (const float*)d_in[2];
    const float* in_b1  = (const float*)d_in[3];
    const float* in_W2  = (const float*)d_in[4];
    const float* in_b2  = (const float*)d_in[5];
    const float* msg_W1 = (const float*)d_in[6];
    const float* msg_b1 = (const float*)d_in[7];
    const float* msg_W2 = (const float*)d_in[8];
    const float* msg_b2 = (const float*)d_in[9];
    const float* upd_W1 = (const float*)d_in[10];
    const float* upd_b1 = (const float*)d_in[11];
    const float* upd_W2 = (const float*)d_in[12];
    const float* upd_b2 = (const float*)d_in[13];
    const float* norm_w = (const float*)d_in[14];
    const float* norm_bv= (const float*)d_in[15];
    const float* norm_ms= (const float*)d_in[16];
    const float* gate_W1= (const float*)d_in[17];
    const float* gate_b1= (const float*)d_in[18];
    const float* gate_W2= (const float*)d_in[19];
    const float* gate_b2= (const float*)d_in[20];
    const float* head_W1= (const float*)d_in[21];
    const float* head_b1= (const float*)d_in[22];
    const float* head_W2= (const float*)d_in[23];
    const float* head_b2= (const float*)d_in[24];
    float* out = (float*)d_out;

    float *hb, *tab, *tbb, *eab, *glb, *ghidb, *partb, *part2b;
    int* knnb;
    uint2 *ih2, *h2, *s2, *agg2, *uh2, *ws;
    cudaGetSymbolAddress((void**)&hb,    g_h);
    cudaGetSymbolAddress((void**)&tab,   g_ta);
    cudaGetSymbolAddress((void**)&tbb,   g_tb);
    cudaGetSymbolAddress((void**)&eab,   g_ea);
    cudaGetSymbolAddress((void**)&knnb,  g_knn);
    cudaGetSymbolAddress((void**)&glb,   g_gl);
    cudaGetSymbolAddress((void**)&ghidb, g_ghid);
    cudaGetSymbolAddress((void**)&partb, g_part);
    cudaGetSymbolAddress((void**)&part2b,g_part2);
    cudaGetSymbolAddress((void**)&ih2,   g_ih2);
    cudaGetSymbolAddress((void**)&h2,    g_h2);
    cudaGetSymbolAddress((void**)&s2,    g_s2);
    cudaGetSymbolAddress((void**)&agg2,  g_agg2);
    cudaGetSymbolAddress((void**)&uh2,   g_uh2);
    cudaGetSymbolAddress((void**)&ws,    g_ws);

    // weight split+pack, KNN, input MLP
    wsplit_kernel<<<(WS_TOTAL + 255) / 256, 256>>>(in_W2, gate_W1, msg_W1, msg_W2,
                                                   upd_W1, upd_W2, ws);
    knn_kernel<<<Nn, 256>>>(x, knnb, eab);
    in_hidden_kernel<<<Nn, DM>>>(x, in_W1, in_b1, ih2);

    // h = in_hidden @ in_W2 + b2   (fp32 h + split h2)
    gemm3s<<<dim3(1, Nn / 128), 256>>>(ih2, ws + WS_INW2, DM,
                                       nullptr, nullptr, 0,
                                       in_b2, nullptr, 1.f, DM,
                                       nullptr, hb, nullptr, h2, DM, 0);

    for (int i = 0; i < Ll; ++i) {
        const float* b1i = msg_b1 + (size_t)i * DH;
        const float* b2i = msg_b2 + (size_t)i * DM;
        const float* W1ce= msg_W1 + (size_t)i * 260 * DH + 2 * DM * DH;  // edge-attr rows
        const float* ub1i= upd_b1 + (size_t)i * DH;
        const float* ub2i= upd_b2 + (size_t)i * DM;
        const float* nwi = norm_w + (size_t)i * DM;
        const float* nbi = norm_bv+ (size_t)i * DM;
        const float* nmi = norm_ms+ (size_t)i * DM;
        const uint2* W1p = ws + WS_L(i);
        const uint2* W2s = ws + WS_L(i) + 65536;
        const uint2* U1a = ws + WS_L(i) + 98304;
        const uint2* U1b = ws + WS_L(i) + 131072;
        const uint2* U2s = ws + WS_L(i) + 163840;

        // [ta | tb] = h @ W1p (+b1 on ta half) : single N=512 GEMM
        gemm3s<<<dim3(4, Nn / 128), 256>>>(h2, W1p, DM,
                                           nullptr, nullptr, 0,
                                           b1i, nullptr, 1.f, 256,
                                           nullptr, tab, tbb, nullptr, 512, 0);
        // s2[n] = split( sum_j silu(ta[n] + tb[src] + ea @ W1[256:260]) )
        edge_kernel<<<Nn, DH>>>(tab, tbb, knnb, eab, W1ce, s2);
        // agg2 = split( s @ W2 + 12*b2 )
        gemm3s<<<dim3(1, Nn / 128), 256>>>(s2, W2s, DH,
                                           nullptr, nullptr, 0,
                                           b2i, nullptr, 12.f, DM,
                                           nullptr, nullptr, nullptr, agg2, DM, 0);
        // uh2 = split( silu(h @ U1a + agg @ U1b + ub1) )
        gemm3s<<<dim3(2, Nn / 128), 256>>>(h2, U1a, DM,
                                           agg2, U1b, DM,
                                           ub1i, nullptr, 1.f, DH,
                                           nullptr, nullptr, nullptr, uh2, DH, 1);
        // h = h + uh @ U2 + ub2   (fp32 only; norm_s3 rewrites h2)
        gemm3s<<<dim3(1, Nn / 128), 256>>>(uh2, U2s, DH,
                                           nullptr, nullptr, 0,
                                           ub2i, nullptr, 1.f, DM,
                                           hb, hb, nullptr, nullptr, DM, 0);
        // graph norm (3 deterministic stages; norm_s3 writes h + h2)
        norm_s1<<<Bg * 8, DM>>>(hb, partb);
        norm_s2<<<Bg * 8, DM>>>(hb, partb, nmi, part2b);
        norm_s3<<<Bg * 8, DM>>>(hb, part2b, nwi, nbi, h2);
    }

    // gate: ghid = tanh(h @ gate_W1 + gate_b1)
    gemm3s<<<dim3(1, Nn / 128), 256>>>(h2, ws + WS_GATE, DM,
                                       nullptr, nullptr, 0,
                                       gate_b1, nullptr, 1.f, DM,
                                       nullptr, ghidb, nullptr, nullptr, DM, 2);
    gl_kernel<<<Nn / 8, 256>>>(ghidb, gate_W2, gate_b2, glb);
    pool_head<<<Bg, 1024>>>(hb, glb, head_W1, head_b1, head_W2, head_b2, out);
}

// round 6
// speedup vs baseline: 1.6316x; 1.6316x over previous
#include <cuda_runtime.h>
#include <math.h>

#define Nn    16384
#define Bg    16
#define NPG   1024
#define Kk    12
#define DM    128
#define DH    256
#define Ll    3

// ---------------- device scratch (no allocs allowed) ----------------
__device__ float g_h  [Nn * DM];
__device__ float g_ta [Nn * DH];
__device__ float g_tb [Nn * DH];
__device__ float g_ea [Nn * Kk * 4];
__device__ int   g_knn[Nn * Kk];
__device__ float g_gl [Nn];
__device__ float g_ghid[Nn * DM];
__device__ float g_part [Bg * 8 * DM];
__device__ float g_part2[Bg * 8 * DM];

// split (hi,lo) buffers, 16B aligned via uint4
__device__ uint4 g_ih2 [Nn * DM / 2];
__device__ uint4 g_h2  [Nn * DM / 2];
__device__ uint4 g_s2  [Nn * DH / 2];
__device__ uint4 g_agg2[Nn * DM / 2];
__device__ uint4 g_uh2 [Nn * DH / 2];

// split weights: layout (uint2 units)
#define WS_TOTAL 622592
#define WS_INW2  0
#define WS_GATE  16384
#define WS_L(l)  (32768 + (l) * 196608)
__device__ uint4 g_ws[WS_TOTAL / 2];

__device__ __forceinline__ float siluf(float v) { return v / (1.f + expf(-v)); }

__device__ __forceinline__ unsigned f2tf32(float f) {
    unsigned u;
    asm("cvt.rna.tf32.f32 %0, %1;" : "=r"(u) : "f"(f));
    return u;
}
__device__ __forceinline__ uint2 split_tf32(float f) {
    unsigned hi = f2tf32(f);
    float res = f - __uint_as_float(hi);
    unsigned lo = f2tf32(res);
    return make_uint2(hi, lo);
}

__device__ __forceinline__ void mma_tf32(float& c0, float& c1, float& c2, float& c3,
                                         unsigned a0, unsigned a1, unsigned a2, unsigned a3,
                                         unsigned b0, unsigned b1) {
    asm volatile("mma.sync.aligned.m16n8k8.row.col.f32.tf32.tf32.f32 "
                 "{%0,%1,%2,%3},{%4,%5,%6,%7},{%8,%9},{%0,%1,%2,%3};"
                 : "+f"(c0), "+f"(c1), "+f"(c2), "+f"(c3)
                 : "r"(a0), "r"(a1), "r"(a2), "r"(a3), "r"(b0), "r"(b1));
}

__device__ __forceinline__ void cpasync16(unsigned s, const void* g) {
    asm volatile("cp.async.cg.shared.global [%0], [%1], 16;" :: "r"(s), "l"(g));
}
__device__ __forceinline__ void cp_commit() {
    asm volatile("cp.async.commit_group;");
}

// ---------------- weight split + pack ----------------
__global__ __launch_bounds__(256) void wsplit_kernel(
    const float* __restrict__ in_W2, const float* __restrict__ gate_W1,
    const float* __restrict__ msg_W1, const float* __restrict__ msg_W2,
    const float* __restrict__ upd_W1, const float* __restrict__ upd_W2,
    uint2* __restrict__ ws) {
    int id = blockIdx.x * 256 + threadIdx.x;
    if (id >= WS_TOTAL) return;
    float v;
    if (id < 16384) v = in_W2[id];
    else if (id < 32768) v = gate_W1[id - 16384];
    else {
        int t = id - 32768;
        int l = t / 196608, r = t % 196608;
        if (r < 65536) {
            int k = r >> 9, n = r & 511;
            const float* W1 = msg_W1 + (size_t)l * 260 * 256;
            v = (n < 256) ? W1[k * 256 + n] : W1[(128 + k) * 256 + (n - 256)];
        } else if (r < 98304) {
            v = msg_W2[(size_t)l * 32768 + (r - 65536)];
        } else if (r < 131072) {
            v = upd_W1[(size_t)l * 65536 + (r - 98304)];
        } else if (r < 163840) {
            v = upd_W1[(size_t)l * 65536 + 32768 + (r - 131072)];
        } else {
            v = upd_W2[(size_t)l * 32768 + (r - 163840)];
        }
    }
    ws[id] = split_tf32(v);
}

// ---------------- KNN + edge attrs ----------------
__global__ __launch_bounds__(256) void knn_kernel(const float* __restrict__ x,
                                                  int* __restrict__ knn,
                                                  float* __restrict__ ea) {
    __shared__ float px[NPG], py[NPG], d2[NPG];
    __shared__ unsigned long long wred[8];
    const float INF = __int_as_float(0x7f800000);
    int n = blockIdx.x;
    int g = n >> 10;
    int li = n & 1023;
    int base = g << 10;
    int tid = threadIdx.x;
    int lane = tid & 31, warp = tid >> 5;
    for (int t = tid; t < NPG; t += 256) {
        px[t] = x[(base + t) * 3 + 1];
        py[t] = x[(base + t) * 3 + 2];
    }
    __syncthreads();
    float mx = px[li], my = py[li];
    for (int t = tid; t < NPG; t += 256) {
        float dx = __fsub_rn(px[t], mx);
        float dy = __fsub_rn(py[t], my);
        float v = __fadd_rn(__fmul_rn(dx, dx), __fmul_rn(dy, dy));
        d2[t] = (t == li) ? INF : v;
    }
    __syncthreads();
    for (int p = 0; p < Kk; ++p) {
        float bd = INF;
        int bi = 1 << 20;
#pragma unroll
        for (int r = 0; r < 4; ++r) {
            int t = tid + r * 256;
            float v = d2[t];
            if (v < bd || (v == bd && t < bi)) { bd = v; bi = t; }
        }
        unsigned long long key = ((unsigned long long)__float_as_uint(bd) << 32) | (unsigned)bi;
#pragma unroll
        for (int o = 16; o; o >>= 1) {
            unsigned long long other = __shfl_xor_sync(0xffffffffu, key, o);
            if (other < key) key = other;
        }
        if (lane == 0) wred[warp] = key;
        __syncthreads();
        if (tid == 0) {
            unsigned long long best = wred[0];
#pragma unroll
            for (int q = 1; q < 8; ++q) if (wred[q] < best) best = wred[q];
            int w = (int)(best & 0xffffffffu);
            knn[n * Kk + p] = base + w;
            float dpx = px[w] - mx, dpy = py[w] - my;
            float dist = sqrtf(dpx * dpx + dpy * dpy + 1e-12f);
            float ds = x[(base + w) * 3] - x[n * 3];
            float* e = ea + (n * Kk + p) * 4;
            e[0] = dpx; e[1] = dpy; e[2] = dist; e[3] = ds;
            d2[w] = INF;
        }
        __syncthreads();
    }
}

// ---------------- input MLP hidden (writes split) ----------------
__global__ void in_hidden_kernel(const float* __restrict__ x,
                                 const float* __restrict__ W1,
                                 const float* __restrict__ b1,
                                 uint2* __restrict__ out2) {
    int n = blockIdx.x;
    int j = threadIdx.x;
    float x0 = x[n * 3], x1 = x[n * 3 + 1], x2 = x[n * 3 + 2];
    float t = b1[j] + x0 * W1[j] + x1 * W1[DM + j] + x2 * W1[2 * DM + j];
    out2[n * DM + j] = split_tf32(siluf(t));
}

// ---------------- 3xTF32 GEMM, cp.async double-buffered (BK=8) ----------------
// C = act( A0@B0 + (A1@B1) + bias + R ), A/B pre-split uint2 (hi,lo).
// cols < colSplit -> Cf0 (ld colSplit, bias) ; cols >= -> Cf1 (ld N-colSplit, bias1).
// Cs0 (split out, ld N) used when colSplit == N.
__global__ __launch_bounds__(256, 2) void gemm3s(
    const uint2* __restrict__ A0, const uint2* __restrict__ B0, int K0,
    const uint2* __restrict__ A1, const uint2* __restrict__ B1, int K1,
    const float* __restrict__ bias, const float* __restrict__ bias1, float biasScale,
    int colSplit,
    const float* __restrict__ R,
    float* __restrict__ Cf0, float* __restrict__ Cf1, uint2* __restrict__ Cs0,
    int N, int act) {
    __shared__ __align__(16) uint2 As2[2][128][12];
    __shared__ __align__(16) uint2 Bs2[2][8][132];
    int tid = threadIdx.x;
    int lane = tid & 31, warp = tid >> 5;
    int wm = warp >> 1, wn = warp & 1;        // 4x2 warps; warp tile 32x64
    int gq = lane >> 2, ctg = lane & 3;
    int rowBase = blockIdx.y * 128, colBase = blockIdx.x * 128;

    int P0 = K0 >> 3;
    int P1 = A1 ? (K1 >> 3) : 0;
    int P = P0 + P1;

    // copy thread mapping
    int arow = tid & 127, ahalf = tid >> 7;   // A: 2x16B at k-cols [ahalf*4, ahalf*4+4)
    int brow = tid >> 5, bcol4 = tid & 31;    // B: 2x16B at uint2-cols bcol4*2, bcol4*2+64

    float c[2][8][4];
#pragma unroll
    for (int t = 0; t < 2; ++t)
#pragma unroll
        for (int j = 0; j < 8; ++j)
#pragma unroll
            for (int e = 0; e < 4; ++e) c[t][j][e] = 0.f;

    auto issue = [&](int p, int buf) {
        const uint2* A; const uint2* B; int K; int k0;
        if (p < P0) { A = A0; B = B0; K = K0; k0 = p << 3; }
        else        { A = A1; B = B1; K = K1; k0 = (p - P0) << 3; }
        const uint2* ga = A + (size_t)(rowBase + arow) * K + k0 + ahalf * 4;
        unsigned sa = (unsigned)__cvta_generic_to_shared(&As2[buf][arow][ahalf * 4]);
        cpasync16(sa, ga);
        cpasync16(sa + 16, ga + 2);
        const uint2* gb = B + (size_t)(k0 + brow) * N + colBase + bcol4 * 2;
        unsigned sb = (unsigned)__cvta_generic_to_shared(&Bs2[buf][brow][bcol4 * 2]);
        cpasync16(sb, gb);
        cpasync16(sb + 512, gb + 64);
    };

    issue(0, 0); cp_commit();
    if (P > 1) issue(1, 1);
    cp_commit();

    for (int p = 0; p < P; ++p) {
        int buf = p & 1;
        asm volatile("cp.async.wait_group 1;");
        __syncthreads();
        uint2 a0[2], a1[2], a2[2], a3[2];
#pragma unroll
        for (int t = 0; t < 2; ++t) {
            int row = wm * 32 + t * 16 + gq;
            a0[t] = As2[buf][row][ctg];
            a1[t] = As2[buf][row + 8][ctg];
            a2[t] = As2[buf][row][ctg + 4];
            a3[t] = As2[buf][row + 8][ctg + 4];
        }
#pragma unroll
        for (int j = 0; j < 8; ++j) {
            int col = wn * 64 + j * 8 + gq;
            uint2 b0 = Bs2[buf][ctg][col];
            uint2 b1 = Bs2[buf][ctg + 4][col];
#pragma unroll
            for (int t = 0; t < 2; ++t) {
                mma_tf32(c[t][j][0], c[t][j][1], c[t][j][2], c[t][j][3],
                         a0[t].x, a1[t].x, a2[t].x, a3[t].x, b0.x, b1.x);
                mma_tf32(c[t][j][0], c[t][j][1], c[t][j][2], c[t][j][3],
                         a0[t].x, a1[t].x, a2[t].x, a3[t].x, b0.y, b1.y);
                mma_tf32(c[t][j][0], c[t][j][1], c[t][j][2], c[t][j][3],
                         a0[t].y, a1[t].y, a2[t].y, a3[t].y, b0.x, b1.x);
            }
        }
        __syncthreads();
        if (p + 2 < P) issue(p + 2, buf);
        cp_commit();
    }

#pragma unroll
    for (int t = 0; t < 2; ++t) {
#pragma unroll
        for (int half = 0; half < 2; ++half) {
            int r = rowBase + wm * 32 + t * 16 + gq + half * 8;
#pragma unroll
            for (int j = 0; j < 8; ++j) {
                int col = colBase + wn * 64 + j * 8 + ctg * 2;
                float v0 = c[t][j][half * 2 + 0];
                float v1 = c[t][j][half * 2 + 1];
                bool first = (col < colSplit);
                const float* bs = first ? bias : bias1;
                int cb = first ? col : col - colSplit;
                if (bs) { v0 += bs[cb] * biasScale; v1 += bs[cb + 1] * biasScale; }
                if (R) {
                    v0 += R[(size_t)r * N + col];
                    v1 += R[(size_t)r * N + col + 1];
                }
                if (act == 1) { v0 = siluf(v0); v1 = siluf(v1); }
                else if (act == 2) { v0 = tanhf(v0); v1 = tanhf(v1); }
                if (first) {
                    if (Cf0) *(float2*)&Cf0[(size_t)r * colSplit + col] = make_float2(v0, v1);
                    if (Cs0) {
                        uint2 s0 = split_tf32(v0), s1 = split_tf32(v1);
                        *(uint4*)&Cs0[(size_t)r * N + col] = make_uint4(s0.x, s0.y, s1.x, s1.y);
                    }
                } else {
                    *(float2*)&Cf1[(size_t)r * (N - colSplit) + cb] = make_float2(v0, v1);
                }
            }
        }
    }
}

// ---------------- per-edge hidden + silu + aggregate (writes split) ----------------
__global__ __launch_bounds__(256) void edge_kernel(const float* __restrict__ ta,
                                                   const float* __restrict__ tb,
                                                   const int* __restrict__ knn,
                                                   const float* __restrict__ ea,
                                                   const float* __restrict__ W1c,
                                                   uint2* __restrict__ s2) {
    __shared__ int   ksh[Kk];
    __shared__ float esh[Kk * 4];
    int n = blockIdx.x;
    int c = threadIdx.x;
    if (c < Kk) ksh[c] = knn[n * Kk + c];
    if (c < Kk * 4) esh[c] = ea[n * Kk * 4 + c];
    __syncthreads();
    float w0 = W1c[c], w1 = W1c[DH + c], w2 = W1c[2 * DH + c], w3 = W1c[3 * DH + c];
    float tav = ta[n * DH + c];
    float acc = 0.f;
#pragma unroll
    for (int j = 0; j < Kk; ++j) {
        int src = ksh[j];
        float v = tav + tb[src * DH + c]
                + esh[4 * j] * w0 + esh[4 * j + 1] * w1
                + esh[4 * j + 2] * w2 + esh[4 * j + 3] * w3;
        acc += siluf(v);
    }
    s2[n * DH + c] = split_tf32(acc);
}

// ---------------- graph norm: 3-kernel deterministic chain ----------------
__global__ void norm_s1(const float* __restrict__ h, float* __restrict__ part) {
    int b = blockIdx.x >> 3, sl = blockIdx.x & 7, c = threadIdx.x;
    int row0 = (b << 10) + (sl << 7);
    float acc = 0.f;
    for (int r = 0; r < 128; ++r) acc += h[(row0 + r) * DM + c];
    part[blockIdx.x * DM + c] = acc;
}
__global__ void norm_s2(float* __restrict__ h, const float* __restrict__ part,
                        const float* __restrict__ ms, float* __restrict__ part2) {
    int b = blockIdx.x >> 3, sl = blockIdx.x & 7, c = threadIdx.x;
    int row0 = (b << 10) + (sl << 7);
    float m = 0.f;
    for (int q = 0; q < 8; ++q) m += part[(b * 8 + q) * DM + c];
    m *= (1.f / 1024.f);
    float mv = m * ms[c];
    float acc = 0.f;
    for (int r = 0; r < 128; ++r) {
        float o = h[(row0 + r) * DM + c] - mv;
        h[(row0 + r) * DM + c] = o;
        acc += o * o;
    }
    part2[blockIdx.x * DM + c] = acc;
}
__global__ void norm_s3(float* __restrict__ h, const float* __restrict__ part2,
                        const float* __restrict__ w, const float* __restrict__ bb,
                        uint2* __restrict__ h2) {
    int b = blockIdx.x >> 3, sl = blockIdx.x & 7, c = threadIdx.x;
    int row0 = (b << 10) + (sl << 7);
    float v = 0.f;
    for (int q = 0; q < 8; ++q) v += part2[(b * 8 + q) * DM + c];
    v *= (1.f / 1024.f);
    float inv = 1.f / sqrtf(v + 1e-5f);
    float wc = w[c] * inv, bc = bb[c];
    for (int r = 0; r < 128; ++r) {
        float val = h[(row0 + r) * DM + c] * wc + bc;
        h[(row0 + r) * DM + c] = val;
        h2[(row0 + r) * DM + c] = split_tf32(val);
    }
}

// ---------------- gate logit GEMV ----------------
__global__ void gl_kernel(const float* __restrict__ ghid, const float* __restrict__ W2,
                          const float* __restrict__ b2, float* __restrict__ gl) {
    int node = blockIdx.x * 8 + (threadIdx.x >> 5);
    int lane = threadIdx.x & 31;
    float acc = 0.f;
#pragma unroll
    for (int r = 0; r < 4; ++r) acc += ghid[node * DM + lane + 32 * r] * W2[lane + 32 * r];
#pragma unroll
    for (int o = 16; o; o >>= 1) acc += __shfl_down_sync(0xffffffffu, acc, o);
    if (lane == 0) gl[node] = acc + b2[0];
}

// ---------------- softmax pool + head ----------------
__global__ __launch_bounds__(1024) void pool_head(const float* __restrict__ h,
                                                  const float* __restrict__ gl,
                                                  const float* __restrict__ hW1,
                                                  const float* __restrict__ hb1,
                                                  const float* __restrict__ hW2,
                                                  const float* __restrict__ hb2,
                                                  float* __restrict__ out) {
    __shared__ float red[1024];
    __shared__ float ash[1024];
    __shared__ float pool[1024];
    __shared__ float pvec[128];
    __shared__ float hid[128];
    int g = blockIdx.x, tid = threadIdx.x;
    float gv = gl[g * NPG + tid];
    red[tid] = gv;
    __syncthreads();
    for (int s = 512; s > 0; s >>= 1) {
        if (tid < s) red[tid] = fmaxf(red[tid], red[tid + s]);
        __syncthreads();
    }
    float gmax = red[0];
    __syncthreads();
    float e = expf(gv - gmax);
    red[tid] = e;
    __syncthreads();
    for (int s = 512; s > 0; s >>= 1) {
        if (tid < s) red[tid] += red[tid + s];
        __syncthreads();
    }
    float ssum = red[0];
    __syncthreads();
    ash[tid] = e / ssum;
    __syncthreads();
    int r = tid >> 7, c = tid & 127;
    float acc = 0.f;
    for (int n = r; n < NPG; n += 8)
        acc += ash[n] * h[(g * NPG + n) * DM + c];
    pool[tid] = acc;
    __syncthreads();
    if (tid < 128) {
        float p = 0.f;
        for (int q = 0; q < 8; ++q) p += pool[q * 128 + tid];
        pvec[tid] = p;
    }
    __syncthreads();
    if (tid < 128) {
        float t = hb1[tid];
        for (int k = 0; k < 128; ++k) t += pvec[k] * hW1[k * DM + tid];
        hid[tid] = siluf(t);
    }
    __syncthreads();
    if (tid < 128) red[tid] = hid[tid] * hW2[tid];
    __syncthreads();
    for (int s = 64; s > 0; s >>= 1) {
        if (tid < s) red[tid] += red[tid + s];
        __syncthreads();
    }
    if (tid == 0) out[g] = red[0] + hb2[0];
}

// ---------------- host orchestration ----------------
extern "C" void kernel_launch(void* const* d_in, const int* in_sizes, int n_in,
                              void* d_out, int out_size) {
    (void)in_sizes; (void)n_in; (void)out_size;
    const float* x      = (const float*)d_in[0];
    const float* in_W1  = (const float*)d_in[2];
    const float* in_b1  = (const float*)d_in[3];
    const float* in_W2  = (const float*)d_in[4];
    const float* in_b2  = (const float*)d_in[5];
    const float* msg_W1 = (const float*)d_in[6];
    const float* msg_b1 = (const float*)d_in[7];
    const float* msg_W2 = (const float*)d_in[8];
    const float* msg_b2 = (const float*)d_in[9];
    const float* upd_W1 = (const float*)d_in[10];
    const float* upd_b1 = (const float*)d_in[11];
    const float* upd_W2 = (const float*)d_in[12];
    const float* upd_b2 = (const float*)d_in[13];
    const float* norm_w = (const float*)d_in[14];
    const float* norm_bv= (const float*)d_in[15];
    const float* norm_ms= (const float*)d_in[16];
    const float* gate_W1= (const float*)d_in[17];
    const float* gate_b1= (const float*)d_in[18];
    const float* gate_W2= (const float*)d_in[19];
    const float* gate_b2= (const float*)d_in[20];
    const float* head_W1= (const float*)d_in[21];
    const float* head_b1= (const float*)d_in[22];
    const float* head_W2= (const float*)d_in[23];
    const float* head_b2= (const float*)d_in[24];
    float* out = (float*)d_out;

    float *hb, *tab, *tbb, *eab, *glb, *ghidb, *partb, *part2b;
    int* knnb;
    uint2 *ih2, *h2, *s2, *agg2, *uh2, *ws;
    cudaGetSymbolAddress((void**)&hb,    g_h);
    cudaGetSymbolAddress((void**)&tab,   g_ta);
    cudaGetSymbolAddress((void**)&tbb,   g_tb);
    cudaGetSymbolAddress((void**)&eab,   g_ea);
    cudaGetSymbolAddress((void**)&knnb,  g_knn);
    cudaGetSymbolAddress((void**)&glb,   g_gl);
    cudaGetSymbolAddress((void**)&ghidb, g_ghid);
    cudaGetSymbolAddress((void**)&partb, g_part);
    cudaGetSymbolAddress((void**)&part2b,g_part2);
    cudaGetSymbolAddress((void**)&ih2,   g_ih2);
    cudaGetSymbolAddress((void**)&h2,    g_h2);
    cudaGetSymbolAddress((void**)&s2,    g_s2);
    cudaGetSymbolAddress((void**)&agg2,  g_agg2);
    cudaGetSymbolAddress((void**)&uh2,   g_uh2);
    cudaGetSymbolAddress((void**)&ws,    g_ws);

    // weight split+pack, KNN, input MLP
    wsplit_kernel<<<(WS_TOTAL + 255) / 256, 256>>>(in_W2, gate_W1, msg_W1, msg_W2,
                                                   upd_W1, upd_W2, ws);
    knn_kernel<<<Nn, 256>>>(x, knnb, eab);
    in_hidden_kernel<<<Nn, DM>>>(x, in_W1, in_b1, ih2);

    // h = in_hidden @ in_W2 + b2   (fp32 h + split h2)
    gemm3s<<<dim3(1, Nn / 128), 256>>>(ih2, ws + WS_INW2, DM,
                                       nullptr, nullptr, 0,
                                       in_b2, nullptr, 1.f, DM,
                                       nullptr, hb, nullptr, h2, DM, 0);

    for (int i = 0; i < Ll; ++i) {
        const float* b1i = msg_b1 + (size_t)i * DH;
        const float* b2i = msg_b2 + (size_t)i * DM;
        const float* W1ce= msg_W1 + (size_t)i * 260 * DH + 2 * DM * DH;
        const float* ub1i= upd_b1 + (size_t)i * DH;
        const float* ub2i= upd_b2 + (size_t)i * DM;
        const float* nwi = norm_w + (size_t)i * DM;
        const float* nbi = norm_bv+ (size_t)i * DM;
        const float* nmi = norm_ms+ (size_t)i * DM;
        const uint2* W1p = ws + WS_L(i);
        const uint2* W2s = ws + WS_L(i) + 65536;
        const uint2* U1a = ws + WS_L(i) + 98304;
        const uint2* U1b = ws + WS_L(i) + 131072;
        const uint2* U2s = ws + WS_L(i) + 163840;

        // [ta | tb] = h @ W1p (+b1 on ta half) : single N=512 GEMM
        gemm3s<<<dim3(4, Nn / 128), 256>>>(h2, W1p, DM,
                                           nullptr, nullptr, 0,
                                           b1i, nullptr, 1.f, 256,
                                           nullptr, tab, tbb, nullptr, 512, 0);
        // s2[n] = split( sum_j silu(ta[n] + tb[src] + ea @ W1[256:260]) )
        edge_kernel<<<Nn, DH>>>(tab, tbb, knnb, eab, W1ce, s2);
        // agg2 = split( s @ W2 + 12*b2 )
        gemm3s<<<dim3(1, Nn / 128), 256>>>(s2, W2s, DH,
                                           nullptr, nullptr, 0,
                                           b2i, nullptr, 12.f, DM,
                                           nullptr, nullptr, nullptr, agg2, DM, 0);
        // uh2 = split( silu(h @ U1a + agg @ U1b + ub1) )
        gemm3s<<<dim3(2, Nn / 128), 256>>>(h2, U1a, DM,
                                           agg2, U1b, DM,
                                           ub1i, nullptr, 1.f, DH,
                                           nullptr, nullptr, nullptr, uh2, DH, 1);
        // h = h + uh @ U2 + ub2   (fp32 only; norm_s3 rewrites h2)
        gemm3s<<<dim3(1, Nn / 128), 256>>>(uh2, U2s, DH,
                                           nullptr, nullptr, 0,
                                           ub2i, nullptr, 1.f, DM,
                                           hb, hb, nullptr, nullptr, DM, 0);
        // graph norm
        norm_s1<<<Bg * 8, DM>>>(hb, partb);
        norm_s2<<<Bg * 8, DM>>>(hb, partb, nmi, part2b);
        norm_s3<<<Bg * 8, DM>>>(hb, part2b, nwi, nbi, h2);
    }

    // gate: ghid = tanh(h @ gate_W1 + gate_b1)
    gemm3s<<<dim3(1, Nn / 128), 256>>>(h2, ws + WS_GATE, DM,
                                       nullptr, nullptr, 0,
                                       gate_b1, nullptr, 1.f, DM,
                                       nullptr, ghidb, nullptr, nullptr, DM, 2);
    gl_kernel<<<Nn / 8, 256>>>(ghidb, gate_W2, gate_b2, glb);
    pool_head<<<Bg, 1024>>>(hb, glb, head_W1, head_b1, head_W2, head_b2, out);
}

// round 7
// speedup vs baseline: 1.8799x; 1.1522x over previous
#include <cuda_runtime.h>
#include <math.h>

#define Nn    16384
#define Bg    16
#define NPG   1024
#define Kk    12
#define DM    128
#define DH    256
#define Ll    3

// ---------------- device scratch (no allocs allowed) ----------------
__device__ float g_h  [Nn * DM];
__device__ float g_ta [Nn * DH];
__device__ float g_tb [Nn * DH];
__device__ float g_ea [Nn * Kk * 4];
__device__ int   g_knn[Nn * Kk];
__device__ float g_gl [Nn];
__device__ float g_ghid[Nn * DM];
__device__ float g_part [Bg * 8 * DM];
__device__ float g_part2[Bg * 8 * DM];

// split (hi,lo) buffers, 16B aligned via uint4
__device__ uint4 g_ih2 [Nn * DM / 2];
__device__ uint4 g_h2  [Nn * DM / 2];
__device__ uint4 g_s2  [Nn * DH / 2];
__device__ uint4 g_agg2[Nn * DM / 2];
__device__ uint4 g_uh2 [Nn * DH / 2];

// split weights: layout (uint2 units)
#define WS_TOTAL 622592
#define WS_INW2  0
#define WS_GATE  16384
#define WS_L(l)  (32768 + (l) * 196608)
__device__ uint4 g_ws[WS_TOTAL / 2];

__device__ __forceinline__ float siluf(float v) { return v / (1.f + expf(-v)); }

__device__ __forceinline__ unsigned f2tf32(float f) {
    unsigned u;
    asm("cvt.rna.tf32.f32 %0, %1;" : "=r"(u) : "f"(f));
    return u;
}
__device__ __forceinline__ uint2 split_tf32(float f) {
    unsigned hi = f2tf32(f);
    float res = f - __uint_as_float(hi);
    unsigned lo = f2tf32(res);
    return make_uint2(hi, lo);
}

__device__ __forceinline__ void mma_tf32(float& c0, float& c1, float& c2, float& c3,
                                         unsigned a0, unsigned a1, unsigned a2, unsigned a3,
                                         unsigned b0, unsigned b1) {
    asm volatile("mma.sync.aligned.m16n8k8.row.col.f32.tf32.tf32.f32 "
                 "{%0,%1,%2,%3},{%4,%5,%6,%7},{%8,%9},{%0,%1,%2,%3};"
                 : "+f"(c0), "+f"(c1), "+f"(c2), "+f"(c3)
                 : "r"(a0), "r"(a1), "r"(a2), "r"(a3), "r"(b0), "r"(b1));
}

__device__ __forceinline__ void cpasync16(unsigned s, const void* g) {
    asm volatile("cp.async.cg.shared.global [%0], [%1], 16;" :: "r"(s), "l"(g));
}
__device__ __forceinline__ void cp_commit() {
    asm volatile("cp.async.commit_group;");
}

// ---------------- weight split + pack ----------------
__global__ __launch_bounds__(256) void wsplit_kernel(
    const float* __restrict__ in_W2, const float* __restrict__ gate_W1,
    const float* __restrict__ msg_W1, const float* __restrict__ msg_W2,
    const float* __restrict__ upd_W1, const float* __restrict__ upd_W2,
    uint2* __restrict__ ws) {
    int id = blockIdx.x * 256 + threadIdx.x;
    if (id >= WS_TOTAL) return;
    float v;
    if (id < 16384) v = in_W2[id];
    else if (id < 32768) v = gate_W1[id - 16384];
    else {
        int t = id - 32768;
        int l = t / 196608, r = t % 196608;
        if (r < 65536) {
            int k = r >> 9, n = r & 511;
            const float* W1 = msg_W1 + (size_t)l * 260 * 256;
            v = (n < 256) ? W1[k * 256 + n] : W1[(128 + k) * 256 + (n - 256)];
        } else if (r < 98304) {
            v = msg_W2[(size_t)l * 32768 + (r - 65536)];
        } else if (r < 131072) {
            v = upd_W1[(size_t)l * 65536 + (r - 98304)];
        } else if (r < 163840) {
            v = upd_W1[(size_t)l * 65536 + 32768 + (r - 131072)];
        } else {
            v = upd_W2[(size_t)l * 32768 + (r - 163840)];
        }
    }
    ws[id] = split_tf32(v);
}

// ---------------- KNN + edge attrs ----------------
__global__ __launch_bounds__(256) void knn_kernel(const float* __restrict__ x,
                                                  int* __restrict__ knn,
                                                  float* __restrict__ ea) {
    __shared__ float px[NPG], py[NPG], d2[NPG];
    __shared__ unsigned long long wred[8];
    const float INF = __int_as_float(0x7f800000);
    int n = blockIdx.x;
    int g = n >> 10;
    int li = n & 1023;
    int base = g << 10;
    int tid = threadIdx.x;
    int lane = tid & 31, warp = tid >> 5;
    for (int t = tid; t < NPG; t += 256) {
        px[t] = x[(base + t) * 3 + 1];
        py[t] = x[(base + t) * 3 + 2];
    }
    __syncthreads();
    float mx = px[li], my = py[li];
    for (int t = tid; t < NPG; t += 256) {
        float dx = __fsub_rn(px[t], mx);
        float dy = __fsub_rn(py[t], my);
        float v = __fadd_rn(__fmul_rn(dx, dx), __fmul_rn(dy, dy));
        d2[t] = (t == li) ? INF : v;
    }
    __syncthreads();
    for (int p = 0; p < Kk; ++p) {
        float bd = INF;
        int bi = 1 << 20;
#pragma unroll
        for (int r = 0; r < 4; ++r) {
            int t = tid + r * 256;
            float v = d2[t];
            if (v < bd || (v == bd && t < bi)) { bd = v; bi = t; }
        }
        unsigned long long key = ((unsigned long long)__float_as_uint(bd) << 32) | (unsigned)bi;
#pragma unroll
        for (int o = 16; o; o >>= 1) {
            unsigned long long other = __shfl_xor_sync(0xffffffffu, key, o);
            if (other < key) key = other;
        }
        if (lane == 0) wred[warp] = key;
        __syncthreads();
        if (tid == 0) {
            unsigned long long best = wred[0];
#pragma unroll
            for (int q = 1; q < 8; ++q) if (wred[q] < best) best = wred[q];
            int w = (int)(best & 0xffffffffu);
            knn[n * Kk + p] = base + w;
            float dpx = px[w] - mx, dpy = py[w] - my;
            float dist = sqrtf(dpx * dpx + dpy * dpy + 1e-12f);
            float ds = x[(base + w) * 3] - x[n * 3];
            float* e = ea + (n * Kk + p) * 4;
            e[0] = dpx; e[1] = dpy; e[2] = dist; e[3] = ds;
            d2[w] = INF;
        }
        __syncthreads();
    }
}

// ---------------- input MLP hidden (writes split) ----------------
__global__ void in_hidden_kernel(const float* __restrict__ x,
                                 const float* __restrict__ W1,
                                 const float* __restrict__ b1,
                                 uint2* __restrict__ out2) {
    int n = blockIdx.x;
    int j = threadIdx.x;
    float x0 = x[n * 3], x1 = x[n * 3 + 1], x2 = x[n * 3 + 2];
    float t = b1[j] + x0 * W1[j] + x1 * W1[DM + j] + x2 * W1[2 * DM + j];
    out2[n * DM + j] = split_tf32(siluf(t));
}

// ---------------- 3xTF32 GEMM: 64x128 block tile, 3-stage cp.async ----------------
// C = act( A0@B0 + (A1@B1) + bias + R ), A/B pre-split uint2 (hi,lo).
// cols < colSplit -> Cf0 (ld colSplit, bias) ; cols >= -> Cf1 (ld N-colSplit, bias1).
// Cs0 (split out, ld N) used when colSplit == N.  grid.y tiles M by 64.
__global__ __launch_bounds__(256, 2) void gemm3s(
    const uint2* __restrict__ A0, const uint2* __restrict__ B0, int K0,
    const uint2* __restrict__ A1, const uint2* __restrict__ B1, int K1,
    const float* __restrict__ bias, const float* __restrict__ bias1, float biasScale,
    int colSplit,
    const float* __restrict__ R,
    float* __restrict__ Cf0, float* __restrict__ Cf1, uint2* __restrict__ Cs0,
    int N, int act) {
    __shared__ __align__(16) uint2 As2[3][64][12];
    __shared__ __align__(16) uint2 Bs2[3][8][132];
    int tid = threadIdx.x;
    int lane = tid & 31, warp = tid >> 5;
    int wm = warp >> 2, wn = warp & 3;        // 2x4 warps; warp tile 32x32
    int gq = lane >> 2, ctg = lane & 3;
    int rowBase = blockIdx.y * 64, colBase = blockIdx.x * 128;

    int P0 = K0 >> 3;
    int P1 = A1 ? (K1 >> 3) : 0;
    int P = P0 + P1;

    float c[2][4][4];
#pragma unroll
    for (int t = 0; t < 2; ++t)
#pragma unroll
        for (int j = 0; j < 4; ++j)
#pragma unroll
            for (int e = 0; e < 4; ++e) c[t][j][e] = 0.f;

    int arow = tid >> 2, achunk = tid & 3;    // A: 64 rows x 4 chunks of 16B
    int brow = tid >> 5, bcol = tid & 31;     // B: 8 rows x (2 chunks of 16B each)

    auto issue = [&](int p, int buf) {
        const uint2* A; const uint2* B; int K; int k0;
        if (p < P0) { A = A0; B = B0; K = K0; k0 = p << 3; }
        else        { A = A1; B = B1; K = K1; k0 = (p - P0) << 3; }
        const uint2* ga = A + (size_t)(rowBase + arow) * K + k0 + achunk * 2;
        unsigned sa = (unsigned)__cvta_generic_to_shared(&As2[buf][arow][achunk * 2]);
        cpasync16(sa, ga);
        const uint2* gb = B + (size_t)(k0 + brow) * N + colBase + bcol * 2;
        unsigned sb = (unsigned)__cvta_generic_to_shared(&Bs2[buf][brow][bcol * 2]);
        cpasync16(sb, gb);
        cpasync16(sb + 512, gb + 64);
    };

    issue(0, 0); cp_commit();
    if (P > 1) issue(1, 1);
    cp_commit();

    for (int p = 0; p < P; ++p) {
        int buf = p % 3;
        asm volatile("cp.async.wait_group 1;");
        __syncthreads();
        uint2 a0[2], a1[2], a2[2], a3[2];
#pragma unroll
        for (int t = 0; t < 2; ++t) {
            int row = wm * 32 + t * 16 + gq;
            a0[t] = As2[buf][row][ctg];
            a1[t] = As2[buf][row + 8][ctg];
            a2[t] = As2[buf][row][ctg + 4];
            a3[t] = As2[buf][row + 8][ctg + 4];
        }
#pragma unroll
        for (int j = 0; j < 4; ++j) {
            int col = wn * 32 + j * 8 + gq;
            uint2 b0 = Bs2[buf][ctg][col];
            uint2 b1 = Bs2[buf][ctg + 4][col];
#pragma unroll
            for (int t = 0; t < 2; ++t) {
                mma_tf32(c[t][j][0], c[t][j][1], c[t][j][2], c[t][j][3],
                         a0[t].x, a1[t].x, a2[t].x, a3[t].x, b0.x, b1.x);
                mma_tf32(c[t][j][0], c[t][j][1], c[t][j][2], c[t][j][3],
                         a0[t].x, a1[t].x, a2[t].x, a3[t].x, b0.y, b1.y);
                mma_tf32(c[t][j][0], c[t][j][1], c[t][j][2], c[t][j][3],
                         a0[t].y, a1[t].y, a2[t].y, a3[t].y, b0.x, b1.x);
            }
        }
        if (p + 2 < P) issue(p + 2, (p + 2) % 3);
        cp_commit();
    }

#pragma unroll
    for (int t = 0; t < 2; ++t) {
#pragma unroll
        for (int half = 0; half < 2; ++half) {
            int r = rowBase + wm * 32 + t * 16 + gq + half * 8;
#pragma unroll
            for (int j = 0; j < 4; ++j) {
                int col = colBase + wn * 32 + j * 8 + ctg * 2;
                float v0 = c[t][j][half * 2 + 0];
                float v1 = c[t][j][half * 2 + 1];
                bool first = (col < colSplit);
                const float* bs = first ? bias : bias1;
                int cb = first ? col : col - colSplit;
                if (bs) { v0 += bs[cb] * biasScale; v1 += bs[cb + 1] * biasScale; }
                if (R) {
                    v0 += R[(size_t)r * N + col];
                    v1 += R[(size_t)r * N + col + 1];
                }
                if (act == 1) { v0 = siluf(v0); v1 = siluf(v1); }
                else if (act == 2) { v0 = tanhf(v0); v1 = tanhf(v1); }
                if (first) {
                    if (Cf0) *(float2*)&Cf0[(size_t)r * colSplit + col] = make_float2(v0, v1);
                    if (Cs0) {
                        uint2 s0 = split_tf32(v0), s1 = split_tf32(v1);
                        *(uint4*)&Cs0[(size_t)r * N + col] = make_uint4(s0.x, s0.y, s1.x, s1.y);
                    }
                } else {
                    *(float2*)&Cf1[(size_t)r * (N - colSplit) + cb] = make_float2(v0, v1);
                }
            }
        }
    }
}

// ---------------- per-edge hidden + silu + aggregate (writes split) ----------------
__global__ __launch_bounds__(256) void edge_kernel(const float* __restrict__ ta,
                                                   const float* __restrict__ tb,
                                                   const int* __restrict__ knn,
                                                   const float* __restrict__ ea,
                                                   const float* __restrict__ W1c,
                                                   uint2* __restrict__ s2) {
    __shared__ int   ksh[Kk];
    __shared__ float esh[Kk * 4];
    int n = blockIdx.x;
    int c = threadIdx.x;
    if (c < Kk) ksh[c] = knn[n * Kk + c];
    if (c < Kk * 4) esh[c] = ea[n * Kk * 4 + c];
    __syncthreads();
    float w0 = W1c[c], w1 = W1c[DH + c], w2 = W1c[2 * DH + c], w3 = W1c[3 * DH + c];
    float tav = ta[n * DH + c];
    float acc = 0.f;
#pragma unroll
    for (int j = 0; j < Kk; ++j) {
        int src = ksh[j];
        float v = tav + tb[src * DH + c]
                + esh[4 * j] * w0 + esh[4 * j + 1] * w1
                + esh[4 * j + 2] * w2 + esh[4 * j + 3] * w3;
        acc += siluf(v);
    }
    s2[n * DH + c] = split_tf32(acc);
}

// ---------------- graph norm: 3-kernel deterministic chain ----------------
__global__ void norm_s1(const float* __restrict__ h, float* __restrict__ part) {
    int b = blockIdx.x >> 3, sl = blockIdx.x & 7, c = threadIdx.x;
    int row0 = (b << 10) + (sl << 7);
    float acc = 0.f;
    for (int r = 0; r < 128; ++r) acc += h[(row0 + r) * DM + c];
    part[blockIdx.x * DM + c] = acc;
}
__global__ void norm_s2(float* __restrict__ h, const float* __restrict__ part,
                        const float* __restrict__ ms, float* __restrict__ part2) {
    int b = blockIdx.x >> 3, sl = blockIdx.x & 7, c = threadIdx.x;
    int row0 = (b << 10) + (sl << 7);
    float m = 0.f;
    for (int q = 0; q < 8; ++q) m += part[(b * 8 + q) * DM + c];
    m *= (1.f / 1024.f);
    float mv = m * ms[c];
    float acc = 0.f;
    for (int r = 0; r < 128; ++r) {
        float o = h[(row0 + r) * DM + c] - mv;
        h[(row0 + r) * DM + c] = o;
        acc += o * o;
    }
    part2[blockIdx.x * DM + c] = acc;
}
__global__ void norm_s3(float* __restrict__ h, const float* __restrict__ part2,
                        const float* __restrict__ w, const float* __restrict__ bb,
                        uint2* __restrict__ h2) {
    int b = blockIdx.x >> 3, sl = blockIdx.x & 7, c = threadIdx.x;
    int row0 = (b << 10) + (sl << 7);
    float v = 0.f;
    for (int q = 0; q < 8; ++q) v += part2[(b * 8 + q) * DM + c];
    v *= (1.f / 1024.f);
    float inv = 1.f / sqrtf(v + 1e-5f);
    float wc = w[c] * inv, bc = bb[c];
    for (int r = 0; r < 128; ++r) {
        float val = h[(row0 + r) * DM + c] * wc + bc;
        h[(row0 + r) * DM + c] = val;
        h2[(row0 + r) * DM + c] = split_tf32(val);
    }
}

// ---------------- gate logit GEMV ----------------
__global__ void gl_kernel(const float* __restrict__ ghid, const float* __restrict__ W2,
                          const float* __restrict__ b2, float* __restrict__ gl) {
    int node = blockIdx.x * 8 + (threadIdx.x >> 5);
    int lane = threadIdx.x & 31;
    float acc = 0.f;
#pragma unroll
    for (int r = 0; r < 4; ++r) acc += ghid[node * DM + lane + 32 * r] * W2[lane + 32 * r];
#pragma unroll
    for (int o = 16; o; o >>= 1) acc += __shfl_down_sync(0xffffffffu, acc, o);
    if (lane == 0) gl[node] = acc + b2[0];
}

// ---------------- softmax pool + head ----------------
__global__ __launch_bounds__(1024) void pool_head(const float* __restrict__ h,
                                                  const float* __restrict__ gl,
                                                  const float* __restrict__ hW1,
                                                  const float* __restrict__ hb1,
                                                  const float* __restrict__ hW2,
                                                  const float* __restrict__ hb2,
                                                  float* __restrict__ out) {
    __shared__ float red[1024];
    __shared__ float ash[1024];
    __shared__ float pool[1024];
    __shared__ float pvec[128];
    __shared__ float hid[128];
    int g = blockIdx.x, tid = threadIdx.x;
    float gv = gl[g * NPG + tid];
    red[tid] = gv;
    __syncthreads();
    for (int s = 512; s > 0; s >>= 1) {
        if (tid < s) red[tid] = fmaxf(red[tid], red[tid + s]);
        __syncthreads();
    }
    float gmax = red[0];
    __syncthreads();
    float e = expf(gv - gmax);
    red[tid] = e;
    __syncthreads();
    for (int s = 512; s > 0; s >>= 1) {
        if (tid < s) red[tid] += red[tid + s];
        __syncthreads();
    }
    float ssum = red[0];
    __syncthreads();
    ash[tid] = e / ssum;
    __syncthreads();
    int r = tid >> 7, c = tid & 127;
    float acc = 0.f;
    for (int n = r; n < NPG; n += 8)
        acc += ash[n] * h[(g * NPG + n) * DM + c];
    pool[tid] = acc;
    __syncthreads();
    if (tid < 128) {
        float p = 0.f;
        for (int q = 0; q < 8; ++q) p += pool[q * 128 + tid];
        pvec[tid] = p;
    }
    __syncthreads();
    if (tid < 128) {
        float t = hb1[tid];
        for (int k = 0; k < 128; ++k) t += pvec[k] * hW1[k * DM + tid];
        hid[tid] = siluf(t);
    }
    __syncthreads();
    if (tid < 128) red[tid] = hid[tid] * hW2[tid];
    __syncthreads();
    for (int s = 64; s > 0; s >>= 1) {
        if (tid < s) red[tid] += red[tid + s];
        __syncthreads();
    }
    if (tid == 0) out[g] = red[0] + hb2[0];
}

// ---------------- host orchestration ----------------
extern "C" void kernel_launch(void* const* d_in, const int* in_sizes, int n_in,
                              void* d_out, int out_size) {
    (void)in_sizes; (void)n_in; (void)out_size;
    const float* x      = (const float*)d_in[0];
    const float* in_W1  = (const float*)d_in[2];
    const float* in_b1  = (const float*)d_in[3];
    const float* in_W2  = (const float*)d_in[4];
    const float* in_b2  = (const float*)d_in[5];
    const float* msg_W1 = (const float*)d_in[6];
    const float* msg_b1 = (const float*)d_in[7];
    const float* msg_W2 = (const float*)d_in[8];
    const float* msg_b2 = (const float*)d_in[9];
    const float* upd_W1 = (const float*)d_in[10];
    const float* upd_b1 = (const float*)d_in[11];
    const float* upd_W2 = (const float*)d_in[12];
    const float* upd_b2 = (const float*)d_in[13];
    const float* norm_w = (const float*)d_in[14];
    const float* norm_bv= (const float*)d_in[15];
    const float* norm_ms= (const float*)d_in[16];
    const float* gate_W1= (const float*)d_in[17];
    const float* gate_b1= (const float*)d_in[18];
    const float* gate_W2= (const float*)d_in[19];
    const float* gate_b2= (const float*)d_in[20];
    const float* head_W1= (const float*)d_in[21];
    const float* head_b1= (const float*)d_in[22];
    const float* head_W2= (const float*)d_in[23];
    const float* head_b2= (const float*)d_in[24];
    float* out = (float*)d_out;

    float *hb, *tab, *tbb, *eab, *glb, *ghidb, *partb, *part2b;
    int* knnb;
    uint2 *ih2, *h2, *s2, *agg2, *uh2, *ws;
    cudaGetSymbolAddress((void**)&hb,    g_h);
    cudaGetSymbolAddress((void**)&tab,   g_ta);
    cudaGetSymbolAddress((void**)&tbb,   g_tb);
    cudaGetSymbolAddress((void**)&eab,   g_ea);
    cudaGetSymbolAddress((void**)&knnb,  g_knn);
    cudaGetSymbolAddress((void**)&glb,   g_gl);
    cudaGetSymbolAddress((void**)&ghidb, g_ghid);
    cudaGetSymbolAddress((void**)&partb, g_part);
    cudaGetSymbolAddress((void**)&part2b,g_part2);
    cudaGetSymbolAddress((void**)&ih2,   g_ih2);
    cudaGetSymbolAddress((void**)&h2,    g_h2);
    cudaGetSymbolAddress((void**)&s2,    g_s2);
    cudaGetSymbolAddress((void**)&agg2,  g_agg2);
    cudaGetSymbolAddress((void**)&uh2,   g_uh2);
    cudaGetSymbolAddress((void**)&ws,    g_ws);

    // weight split+pack, KNN, input MLP
    wsplit_kernel<<<(WS_TOTAL + 255) / 256, 256>>>(in_W2, gate_W1, msg_W1, msg_W2,
                                                   upd_W1, upd_W2, ws);
    knn_kernel<<<Nn, 256>>>(x, knnb, eab);
    in_hidden_kernel<<<Nn, DM>>>(x, in_W1, in_b1, ih2);

    // h = in_hidden @ in_W2 + b2   (fp32 h + split h2)
    gemm3s<<<dim3(1, Nn / 64), 256>>>(ih2, ws + WS_INW2, DM,
                                      nullptr, nullptr, 0,
                                      in_b2, nullptr, 1.f, DM,
                                      nullptr, hb, nullptr, h2, DM, 0);

    for (int i = 0; i < Ll; ++i) {
        const float* b1i = msg_b1 + (size_t)i * DH;
        const float* b2i = msg_b2 + (size_t)i * DM;
        const float* W1ce= msg_W1 + (size_t)i * 260 * DH + 2 * DM * DH;
        const float* ub1i= upd_b1 + (size_t)i * DH;
        const float* ub2i= upd_b2 + (size_t)i * DM;
        const float* nwi = norm_w + (size_t)i * DM;
        const float* nbi = norm_bv+ (size_t)i * DM;
        const float* nmi = norm_ms+ (size_t)i * DM;
        const uint2* W1p = ws + WS_L(i);
        const uint2* W2s = ws + WS_L(i) + 65536;
        const uint2* U1a = ws + WS_L(i) + 98304;
        const uint2* U1b = ws + WS_L(i) + 131072;
        const uint2* U2s = ws + WS_L(i) + 163840;

        // [ta | tb] = h @ W1p (+b1 on ta half) : single N=512 GEMM
        gemm3s<<<dim3(4, Nn / 64), 256>>>(h2, W1p, DM,
                                          nullptr, nullptr, 0,
                                          b1i, nullptr, 1.f, 256,
                                          nullptr, tab, tbb, nullptr, 512, 0);
        // s2[n] = split( sum_j silu(ta[n] + tb[src] + ea @ W1[256:260]) )
        edge_kernel<<<Nn, DH>>>(tab, tbb, knnb, eab, W1ce, s2);
        // agg2 = split( s @ W2 + 12*b2 )
        gemm3s<<<dim3(1, Nn / 64), 256>>>(s2, W2s, DH,
                                          nullptr, nullptr, 0,
                                          b2i, nullptr, 12.f, DM,
                                          nullptr, nullptr, nullptr, agg2, DM, 0);
        // uh2 = split( silu(h @ U1a + agg @ U1b + ub1) )
        gemm3s<<<dim3(2, Nn / 64), 256>>>(h2, U1a, DM,
                                          agg2, U1b, DM,
                                          ub1i, nullptr, 1.f, DH,
                                          nullptr, nullptr, nullptr, uh2, DH, 1);
        // h = h + uh @ U2 + ub2   (fp32 only; norm_s3 rewrites h2)
        gemm3s<<<dim3(1, Nn / 64), 256>>>(uh2, U2s, DH,
                                          nullptr, nullptr, 0,
                                          ub2i, nullptr, 1.f, DM,
                                          hb, hb, nullptr, nullptr, DM, 0);
        // graph norm
        norm_s1<<<Bg * 8, DM>>>(hb, partb);
        norm_s2<<<Bg * 8, DM>>>(hb, partb, nmi, part2b);
        norm_s3<<<Bg * 8, DM>>>(hb, part2b, nwi, nbi, h2);
    }

    // gate: ghid = tanh(h @ gate_W1 + gate_b1)
    gemm3s<<<dim3(1, Nn / 64), 256>>>(h2, ws + WS_GATE, DM,
                                      nullptr, nullptr, 0,
                                      gate_b1, nullptr, 1.f, DM,
                                      nullptr, ghidb, nullptr, nullptr, DM, 2);
    gl_kernel<<<Nn / 8, 256>>>(ghidb, gate_W2, gate_b2, glb);
    pool_head<<<Bg, 1024>>>(hb, glb, head_W1, head_b1, head_W2, head_b2, out);
}